// round 16
// baseline (speedup 1.0000x reference)
#include <cuda_runtime.h>
#include <cstdint>
#include <type_traits>

// VelocityLoss on GB300 — single-chain cp.async 3-slab ring with
// issue-before-compute, in 128-thread blocks:
//   - per-warp smem 3 slabs (2400B) + tv (336B) -> 30.1KB/block
//     -> 7 blocks/SM = 28 resident warps (R15's ring only got 24)
//   - NBLK=3840 -> 3.7 waves (R14/R15 had 1.6 -> big drain tail)
//   - schedule gives stages S2/S3 two compute intervals of latency cover:
//     issue S0,S1 | waitg<1> issue S2 compute S0 issue S3 |
//     waitg<2> compute S1 | waitg<1> compute S2 | waitg<0> compute S3

namespace {
constexpr int B_  = 512;
constexpr int S_  = 480;
constexpr int F_  = 149;
constexpr int VF_ = 5;
constexpr int CH  = 16;                   // rows per warp chunk
constexpr int CPB = S_ / CH;              // 30
constexpr int WPB = 4;                    // 128 threads
constexpr int NBLK = B_ * CPB / WPB;      // 3840
constexpr int STG = 600;                  // floats per slab (2400B)
constexpr int TVF = 84;                   // floats per tv buffer (336B)
constexpr int PWF = 3 * STG + TVF;        // per-warp floats (1884)
constexpr int SMEM_BYTES = WPB * PWF * 4; // 30144
}

__device__ double g_acc[3] = {0.0, 0.0, 0.0};
__device__ unsigned int g_ticket = 0;

// lane -> joint, part groups shuffle-aligned:
// lanes 0-7 part0, 8-11 part1, 12-15 part2, 16-19 part3, 20-23 part4
__constant__ int c_j[24] = {
    8, 9, 10, 11, 12, 21, 22, 23,
    0, 1, 2, 3,
    4, 5, 6, 7,
    13, 14, 15, 16,
    17, 18, 19, 20
};
__constant__ float c_wl[24] = {
    1.f/9, 1.f/9, 1.f/9, 1.f/9, 1.f/9, 1.f/9, 2.f/9, 1.f/9,
    0.1f, 0.2f, 0.3f, 0.4f,
    0.1f, 0.2f, 0.3f, 0.4f,
    0.1f, 0.2f, 0.3f, 0.4f,
    0.1f, 0.2f, 0.3f, 0.4f
};

__device__ __forceinline__ void cp16(unsigned sdst, const void* gsrc) {
    asm volatile("cp.async.cg.shared.global [%0], [%1], 16;" :: "r"(sdst), "l"(gsrc));
}
__device__ __forceinline__ void cp4(unsigned sdst, const void* gsrc) {
    asm volatile("cp.async.ca.shared.global [%0], [%1], 4;" :: "r"(sdst), "l"(gsrc));
}
__device__ __forceinline__ void commitg() { asm volatile("cp.async.commit_group;"); }
template <int N> __device__ __forceinline__ void waitg() {
    asm volatile("cp.async.wait_group %0;" :: "n"(N));
}

__global__ void __launch_bounds__(128, 7) vel_loss_ring7(
    const float* __restrict__ pred,   // (B, S, F)
    const float* __restrict__ tvft,   // (B, S+1, VF)
    const float* __restrict__ meanv,  // (F,)
    const float* __restrict__ stdv,   // (F,)
    float* __restrict__ out)
{
    extern __shared__ __align__(16) float dyn[];
    __shared__ double sA[WPB], sB[WPB], sC[WPB];

    const int tid  = threadIdx.x;
    const int lane = tid & 31;
    const int warp = tid >> 5;
    const int idx  = blockIdx.x * WPB + warp;   // chunk id
    const int b    = idx / CPB;
    const int s0   = (idx % CPB) * CH;
    const unsigned FULL = 0xffffffffu;

    float* wbase = dyn + warp * PWF;
    float* slab[3] = { wbase, wbase + STG, wbase + 2 * STG };
    float* tvp0 = wbase + 3 * STG;
    unsigned sslab[3];
    #pragma unroll
    for (int i = 0; i < 3; ++i) sslab[i] = (unsigned)__cvta_generic_to_shared(slab[i]);
    const unsigned stv = (unsigned)__cvta_generic_to_shared(tvp0);

    // per-lane joint parameters
    int jj = 0; float w = 0.f;
    float sp0 = 0, sp1 = 0, sp2 = 0, rv0 = 0, rv1 = 0, rv2 = 0;
    float a0c = 0, a1c = 0, a2c = 0;
    const bool act = (lane < 24);
    if (act) {
        jj = c_j[lane] * 3;
        w  = c_wl[lane];
        sp0 = stdv[jj];     sp1 = stdv[jj + 1];     sp2 = stdv[jj + 2];
        rv0 = 1.0f / stdv[72 + jj];
        rv1 = 1.0f / stdv[72 + jj + 1];
        rv2 = 1.0f / stdv[72 + jj + 2];
        a0c = meanv[72 + jj]     * rv0;
        a1c = meanv[72 + jj + 1] * rv1;
        a2c = meanv[72 + jj + 2] * rv2;
    }
    int pidx = -1;
    if      (lane == 0)  pidx = 0;
    else if (lane == 8)  pidx = 1;
    else if (lane == 12) pidx = 2;
    else if (lane == 16) pidx = 3;
    else if (lane == 20) pidx = 4;
    float mfrf = 0.f, rf = 0.f;
    if (pidx >= 0) {
        rf = 1.0f / stdv[144 + pidx];
        mfrf = meanv[144 + pidx] * rf;
    }
    const int pid0 = (pidx >= 0) ? pidx : 0;

    float accA = 0.f, accB0 = 0.f, accC = 0.f;
    float p0 = 0.f, p1 = 0.f, p2 = 0.f;

    // ---- prologue: prev-row / s==0 zero-target term (plain LDG) ----
    const bool first = (s0 == 0);
    {
        const float* r0 = pred + ((size_t)(b * S_ + s0)) * F_;
        if (first) {
            if (act) {
                p0 = r0[jj]; p1 = r0[jj + 1]; p2 = r0[jj + 2];
                const float q0 = r0[77 + jj], q1 = r0[78 + jj], q2 = r0[79 + jj];
                accB0 = q0 * q0 + q1 * q1 + q2 * q2;
            }
        } else if (act) {
            const float* rp = r0 - F_;
            p0 = rp[jj]; p1 = rp[jj + 1]; p2 = rp[jj + 2];
        }
    }
    const int sBeg = first ? 1 : s0;
    const bool lastChunk = (idx == B_ * CPB - 1);

    // ---- chunk-invariant loader state (stage stride 2384B % 16 == 0) ----
    const uintptr_t gb0 = (uintptr_t)(pred + (size_t)(b * S_ + sBeg) * F_);
    const char* ga0 = (const char*)(gb0 & ~(uintptr_t)15);
    const int db  = (int)(gb0 & 15);
    const int df  = db >> 2;
    const int nch = (db + 4 * F_ * 4 + 15) >> 4;

    auto loadStage = [&](int t, int sl, bool useCp4) {
        const char* ga = ga0 + (size_t)t * (4 * F_ * 4);
        const unsigned sdst = sslab[sl];
        if (!useCp4) {
            #pragma unroll
            for (int i = 0; i < 5; ++i) {
                const int c = lane + i * 32;
                if (c < nch) cp16(sdst + c * 16, ga + c * 16);
            }
        } else {
            const int nw = (db + 4 * F_ * 4) >> 2;
            for (int i = lane; i < nw; i += 32)
                cp4(sdst + i * 4, ga + i * 4);
        }
        commitg();
    };

    // ---- tv staging: 16 rows x 5 floats, contiguous ----
    const size_t ftv = (size_t)(b * (S_ + 1) + sBeg) * VF_;
    const uintptr_t gtv = (uintptr_t)(tvft + ftv);
    const int dtv4 = (int)(ftv & 3);

    auto computeBatch = [&](int j0, int sl, auto nrc) {
        constexpr int NR = decltype(nrc)::value;
        const float* r0 = slab[sl] + df;
        const float* tvp = tvp0 + dtv4 + j0 * VF_ + pid0;
        float trv[NR];
        #pragma unroll
        for (int k = 0; k < NR; ++k) trv[k] = tvp[k * VF_];
        float contrib[NR];
        #pragma unroll
        for (int k = 0; k < NR; ++k) {
            contrib[k] = 0.f;
            if (act) {
                const float* rr = r0 + k * F_;
                const float c0 = rr[jj], c1 = rr[jj + 1], c2 = rr[jj + 2];
                const float q0 = rr[77 + jj], q1 = rr[78 + jj], q2 = rr[79 + jj];
                const float v0 = (c0 - p0) * sp0;
                const float v1 = (c1 - p1) * sp1;
                const float v2 = (c2 - p2) * sp2;
                const float d0 = q0 + a0c - v0 * rv0;
                const float d1 = q1 + a1c - v1 * rv1;
                const float d2 = q2 + a2c - v2 * rv2;
                accA += d0 * d0 + d1 * d1 + d2 * d2;
                contrib[k] = sqrtf(v0 * v0 + v1 * v1 + v2 * v2) * w;
                p0 = c0; p1 = c1; p2 = c2;
            }
        }
        float g4v[NR], g8v[NR];
        #pragma unroll
        for (int k = 0; k < NR; ++k) g4v[k] = contrib[k] + __shfl_xor_sync(FULL, contrib[k], 1);
        #pragma unroll
        for (int k = 0; k < NR; ++k) g4v[k] += __shfl_xor_sync(FULL, g4v[k], 2);
        #pragma unroll
        for (int k = 0; k < NR; ++k) g8v[k] = g4v[k] + __shfl_xor_sync(FULL, g4v[k], 4);
        if (pidx >= 0) {
            #pragma unroll
            for (int k = 0; k < NR; ++k) {
                const float f = (pidx == 0) ? g8v[k] : g4v[k];
                const float d = trv[k] + mfrf - f * rf;
                accC += d * d;
            }
        }
    };

    constexpr auto N4 = std::integral_constant<int, 4>{};
    constexpr auto N3 = std::integral_constant<int, 3>{};

    // ---- mainloop: 3-slab ring, issue-before-compute ----
    // groups: G0 = tv + S0(sl0), G1 = S1(sl1), G2 = S2(sl2), G3 = S3(sl0)
    {
        const int nchTV = ((int)(gtv & 15) + 16 * VF_ * 4 + 15) >> 4;   // <= 21
        if (lane < nchTV) cp16(stv + lane * 16, (const char*)(gtv & ~(uintptr_t)15) + lane * 16);
    }
    loadStage(0, 0, false);          // G0
    loadStage(1, 1, false);          // G1
    waitg<1>(); __syncwarp();        // G0 done
    loadStage(2, 2, false);          // G2 (2 compute intervals of cover)
    computeBatch(0, 0, N4);          // S0 (frees slab0)
    loadStage(3, 0, lastChunk);      // G3 -> slab0
    waitg<2>(); __syncwarp();        // G1 done (G2,G3 may pend)
    computeBatch(4, 1, N4);          // S1
    waitg<1>(); __syncwarp();        // G2 done
    computeBatch(8, 2, N4);          // S2
    waitg<0>(); __syncwarp();        // G3 done
    if (!first) computeBatch(12, 0, N4);
    else        computeBatch(12, 0, N3);   // rows 13..15 (stage covers 13..16)

    // ---- reductions ----
    #pragma unroll
    for (int off = 16; off; off >>= 1) {
        accA  += __shfl_xor_sync(FULL, accA, off);
        accB0 += __shfl_xor_sync(FULL, accB0, off);
        accC  += __shfl_xor_sync(FULL, accC, off);
    }
    if (lane == 0) {
        sA[warp] = (double)accA;
        sB[warp] = (double)accB0;
        sC[warp] = (double)accC;
    }
    __syncthreads();

    if (warp == 0) {
        double a  = (lane < WPB) ? sA[lane] : 0.0;
        double bb = (lane < WPB) ? sB[lane] : 0.0;
        double c  = (lane < WPB) ? sC[lane] : 0.0;
        #pragma unroll
        for (int off = 2; off; off >>= 1) {
            a  += __shfl_xor_sync(FULL, a, off);
            bb += __shfl_xor_sync(FULL, bb, off);
            c  += __shfl_xor_sync(FULL, c, off);
        }
        if (lane == 0) {
            atomicAdd(&g_acc[0], a);
            atomicAdd(&g_acc[1], bb);
            atomicAdd(&g_acc[2], c);
            __threadfence();
            const unsigned t = atomicAdd(&g_ticket, 1u);
            if (t == (unsigned)(NBLK - 1)) {
                __threadfence();
                volatile double* ga = g_acc;
                const double A  = ga[0];
                const double B0 = ga[1];
                const double C  = ga[2];
                const double nA  = (double)B_ * (double)(S_ - 1) * 72.0;
                const double nB2 = (double)B_ * 72.0;
                const double nC  = (double)B_ * (double)(S_ - 1) * (double)VF_;
                const double loss1 = 10.0 * A / nA + 20.0 * B0 / nB2;
                const double loss2 = 10.0 * C / nC;
                out[0] = (float)(2.0 * loss1 + 1.5 * loss2);
                ga[0] = 0.0; ga[1] = 0.0; ga[2] = 0.0;
                g_ticket = 0;
            }
        }
    }
}

extern "C" void kernel_launch(void* const* d_in, const int* in_sizes, int n_in,
                              void* d_out, int out_size) {
    const float* pred = (const float*)d_in[0];   // predict_seq (B,S,F)
    // d_in[1] = _train_x1 (unused), d_in[2] = _train_x2 (unused)
    const float* tvft = (const float*)d_in[3];   // _true_vel_factor (B,S+1,VF)
    const float* mean = (const float*)d_in[4];   // _mean (F,)
    const float* stdv = (const float*)d_in[5];   // _std (F,)

    vel_loss_ring7<<<NBLK, 128, SMEM_BYTES>>>(pred, tvft, mean, stdv, (float*)d_out);
}